// round 16
// baseline (speedup 1.0000x reference)
#include <cuda_runtime.h>
#include <cuda_fp16.h>
#include <math.h>
#include <stdint.h>

#define N_PIX   131072
typedef unsigned long long u64;

// Output layout offsets (flattened tuple, float32) — total 8651778
#define QUANT_OFF 0
#define LOSS_OFF  8388608
#define PERP_OFF  8388609
#define IDX_OFF   8388610
#define NCS_OFF   8519682
#define NEMA_OFF  8520706
#define NEMB_OFF  8586242

// Scratch (device globals; no allocation allowed)
__device__ int   g_idx[N_PIX];
__device__ float g_embT[64 * 1024];                  // embT[d][k] for fbx
__device__ float g_esqh[1024];                       // -0.5*||e||^2
__device__ float g_lesq[1024];                       // ||e - hi(e)||^2
__device__ float g_counts[1024];
__device__ float g_dwp[8 * 65536];                   // 8-way privatized dw
__device__ float g_scl[1024];
__device__ float g_loss;
__device__ float g_maxne;                            // max_k ||e_k||
__device__ float g_maxnle;                           // max_k ||lo(e_k)||
// packed fp16-hi codebook: [chunk 16][kstep 4][n 64][j 8] half2
__device__ __align__(128) __half g_Bpk[16 * 4096];
__device__ int   g_fb_list[N_PIX];
__device__ int   g_fb_count;
__device__ __align__(16) u64 g_fbres4[N_PIX * 4];    // per-quarter exact packed results

// ---------------------------------------------------------------------------
// helpers (base PTX only)
// ---------------------------------------------------------------------------
__device__ __forceinline__ uint32_t smem_u32(const void* p) {
    uint32_t a;
    asm("{ .reg .u64 t; cvta.to.shared.u64 t, %1; cvt.u32.u64 %0, t; }" : "=r"(a) : "l"(p));
    return a;
}
__device__ __forceinline__ void mma16(float& d0, float& d1, float& d2, float& d3,
                                      const uint32_t* a, uint32_t b0, uint32_t b1) {
    asm volatile(
        "mma.sync.aligned.m16n8k16.row.col.f32.f16.f16.f32 "
        "{%0,%1,%2,%3}, {%4,%5,%6,%7}, {%8,%9}, {%0,%1,%2,%3};"
        : "+f"(d0), "+f"(d1), "+f"(d2), "+f"(d3)
        : "r"(a[0]), "r"(a[1]), "r"(a[2]), "r"(a[3]), "r"(b0), "r"(b1));
}
#define CP_ASYNC16(dst, src) \
    asm volatile("cp.async.cg.shared.global [%0], [%1], 16;" :: "r"(dst), "l"(src) : "memory")
#define CP_COMMIT() asm volatile("cp.async.commit_group;" ::: "memory")
#define CP_WAIT1()  asm volatile("cp.async.wait_group 1;" ::: "memory")
#define CP_WAIT0()  asm volatile("cp.async.wait_group 0;" ::: "memory")

__device__ __forceinline__ void red_v4(float* p, float a, float b, float c, float d) {
    asm volatile("red.global.add.v4.f32 [%0], {%1,%2,%3,%4};"
                 :: "l"(p), "f"(a), "f"(b), "f"(c), "f"(d) : "memory");
}
__device__ __forceinline__ uint32_t packh2(float x0, float x1) {
    __half2 hh = __halves2half2(__float2half_rn(x0), __float2half_rn(x1));
    return *(uint32_t*)&hh;
}
// pack score with code index in low 10 mantissa bits (branchless argmax carrier)
__device__ __forceinline__ float packsi(float s, int code) {
    return __uint_as_float((__float_as_uint(s) & 0xFFFFFC00u) | (uint32_t)code);
}
// branchless best-2 insert (b1 = max, b2 = runner-up)
__device__ __forceinline__ void best2(float& b1, float& b2, float s) {
    float t = fminf(s, b1);
    b1 = fmaxf(b1, s);
    b2 = fmaxf(b2, t);
}
// exact ordered encoding: u64 compare == (score desc, index asc) fp32 compare
__device__ __forceinline__ u64 packord(float s, int idx) {
    uint32_t u = __float_as_uint(s);
    u = (u & 0x80000000u) ? ~u : (u | 0x80000000u);
    return ((u64)u << 32) | (uint32_t)(1023 - idx);
}

// ---------------------------------------------------------------------------
// Kernel 1: prep — fp16-hi packed codebook, embT, esqh, lo-norms, zero accums
// ---------------------------------------------------------------------------
__global__ void prep_kernel(const float* __restrict__ embed) {
    int k = blockIdx.x;
    int t = threadIdx.x;
    float v = embed[k * 64 + t];
    g_embT[t * 1024 + k] = v;
    #pragma unroll
    for (int i = 0; i < 8; i++) g_dwp[i * 65536 + k * 64 + t] = 0.0f;

    __half hv = __float2half_rn(v);
    float lo = v - __half2float(hv);

    int c = k >> 6, n = k & 63, s = t >> 4, dl = t & 15, p = dl >> 1, h = dl & 1;
    int j = ((p & 3) << 1) | (p >> 2);
    g_Bpk[c * 4096 + (s * 64 + n) * 16 + j * 2 + h] = hv;

    float sq = v * v;
    float sql = lo * lo;
    #pragma unroll
    for (int o = 16; o; o >>= 1) {
        sq  += __shfl_down_sync(0xffffffffu, sq, o);
        sql += __shfl_down_sync(0xffffffffu, sql, o);
    }
    __shared__ float sm[2], sm2[2];
    if ((t & 31) == 0) { sm[t >> 5] = sq; sm2[t >> 5] = sql; }
    __syncthreads();
    if (t == 0) {
        g_esqh[k] = -0.5f * (sm[0] + sm[1]);
        g_lesq[k] = sm2[0] + sm2[1];
        g_counts[k] = 0.0f;
        if (k == 0) g_loss = 0.0f;
    }
}

// ---------------------------------------------------------------------------
// Kernel 1b: max norms + fb counter reset
// ---------------------------------------------------------------------------
__global__ void maxk_kernel() {
    __shared__ float sm[1024];
    __shared__ float sm2[1024];
    int t = threadIdx.x;
    sm[t] = g_esqh[t];
    sm2[t] = g_lesq[t];
    __syncthreads();
    for (int o = 512; o; o >>= 1) {
        if (t < o) {
            sm[t] = fminf(sm[t], sm[t + o]);
            sm2[t] = fmaxf(sm2[t], sm2[t + o]);
        }
        __syncthreads();
    }
    if (t == 0) {
        g_maxne = sqrtf(-2.0f * sm[0]);
        g_maxnle = sqrtf(sm2[0]);
        g_fb_count = 0;
    }
}

// ---------------------------------------------------------------------------
// Kernel 2: hh-only fp16 argmin via mma.sync; branchless packed best-2.
// Exact per-pixel lo-norm error bound; uncertain -> g_fb_list (+zeroed slots).
// ---------------------------------------------------------------------------
__global__ void __launch_bounds__(256) argmin_mma(const float* __restrict__ in,
                                                  float* __restrict__ out) {
    __shared__ __align__(16) __half Bsm[8192];    // 2 bufs x 8KB
    __shared__ float esqs[1024];
    uint32_t smb = smem_u32(Bsm);

    const int tid = threadIdx.x;
    const int w   = tid >> 5;
    const int ln  = tid & 31;
    const int g   = ln >> 2;
    const int t   = ln & 3;
    const int p0  = blockIdx.x * 128;
    const int bimg = p0 >> 12;
    const int hw0  = p0 & 4095;

    #pragma unroll
    for (int jj = 0; jj < 2; jj++) {
        int idx = tid + jj * 256;
        CP_ASYNC16(smb + idx * 16, (const char*)g_Bpk + idx * 16);
    }
    CP_COMMIT();

    #pragma unroll
    for (int i = 0; i < 4; i++) esqs[tid + i * 256] = g_esqh[tid + i * 256];

    uint32_t ah[4][4];
    float ssa = 0.0f, ssb = 0.0f, ssla = 0.0f, sslb = 0.0f;
    {
        const float* ap = in + (size_t)bimg * 262144 + hw0 + w * 16 + g;
        #pragma unroll
        for (int s = 0; s < 4; s++) {
            int d0 = 16 * s + 2 * t;
            float xa0 = ap[d0 * 4096],           xa1 = ap[(d0 + 1) * 4096];
            float xb0 = ap[d0 * 4096 + 8],       xb1 = ap[(d0 + 1) * 4096 + 8];
            float ya0 = ap[(d0 + 8) * 4096],     ya1 = ap[(d0 + 9) * 4096];
            float yb0 = ap[(d0 + 8) * 4096 + 8], yb1 = ap[(d0 + 9) * 4096 + 8];
            ah[s][0] = packh2(xa0, xa1);
            ah[s][1] = packh2(xb0, xb1);
            ah[s][2] = packh2(ya0, ya1);
            ah[s][3] = packh2(yb0, yb1);
            ssa += xa0 * xa0 + xa1 * xa1 + ya0 * ya0 + ya1 * ya1;
            ssb += xb0 * xb0 + xb1 * xb1 + yb0 * yb0 + yb1 * yb1;
            float l;
            l = xa0 - __half2float(__float2half_rn(xa0)); ssla += l * l;
            l = xa1 - __half2float(__float2half_rn(xa1)); ssla += l * l;
            l = ya0 - __half2float(__float2half_rn(ya0)); ssla += l * l;
            l = ya1 - __half2float(__float2half_rn(ya1)); ssla += l * l;
            l = xb0 - __half2float(__float2half_rn(xb0)); sslb += l * l;
            l = xb1 - __half2float(__float2half_rn(xb1)); sslb += l * l;
            l = yb0 - __half2float(__float2half_rn(yb0)); sslb += l * l;
            l = yb1 - __half2float(__float2half_rn(yb1)); sslb += l * l;
        }
        ssa += __shfl_xor_sync(0xffffffffu, ssa, 1);
        ssa += __shfl_xor_sync(0xffffffffu, ssa, 2);
        ssb += __shfl_xor_sync(0xffffffffu, ssb, 1);
        ssb += __shfl_xor_sync(0xffffffffu, ssb, 2);
        ssla += __shfl_xor_sync(0xffffffffu, ssla, 1);
        ssla += __shfl_xor_sync(0xffffffffu, ssla, 2);
        sslb += __shfl_xor_sync(0xffffffffu, sslb, 1);
        sslb += __shfl_xor_sync(0xffffffffu, sslb, 2);
    }

    float b1a = -3.4e38f, b2a = -3.4e38f;   // row g   (packed score|idx)
    float b1b = -3.4e38f, b2b = -3.4e38f;   // row g+8

    for (int c = 0; c < 16; c++) {
        const int buf = c & 1;
        if (c < 15) {
            int nb = (c + 1) & 1;
            #pragma unroll
            for (int jj = 0; jj < 2; jj++) {
                int idx = tid + jj * 256;
                CP_ASYNC16(smb + nb * 8192 + idx * 16,
                           (const char*)g_Bpk + (c + 1) * 8192 + idx * 16);
            }
            CP_COMMIT();
            CP_WAIT1();
        } else {
            CP_WAIT0();
        }
        __syncthreads();

        const uint32_t bb = smb + buf * 8192;
        const int kbase = c * 64;

        #pragma unroll
        for (int nt = 0; nt < 8; nt++) {
            const int nb_ = nt * 8 + g;
            const int code0 = kbase + nt * 8 + 2 * t;
            float e0 = esqs[code0], e1 = esqs[code0 + 1];
            float c0 = e0, c1 = e1, c2 = e0, c3 = e1;   // bias folded into accum
            #pragma unroll
            for (int s = 0; s < 4; s++) {
                uint32_t offh = bb + (s * 64 + nb_) * 32 + 8 * t;
                uint32_t bh0, bh1;
                asm volatile("ld.shared.v2.b32 {%0,%1}, [%2];" : "=r"(bh0), "=r"(bh1) : "r"(offh));
                mma16(c0, c1, c2, c3, ah[s], bh0, bh1);
            }
            best2(b1a, b2a, packsi(c0, code0));
            best2(b1a, b2a, packsi(c1, code0 + 1));
            best2(b1b, b2b, packsi(c2, code0));
            best2(b1b, b2b, packsi(c3, code0 + 1));
        }
        __syncthreads();
    }

    // merge best-2 across the 4 t-lanes
    #pragma unroll
    for (int o = 1; o <= 2; o <<= 1) {
        float x1 = __shfl_xor_sync(0xffffffffu, b1a, o);
        float x2 = __shfl_xor_sync(0xffffffffu, b2a, o);
        b2a = fmaxf(fmaxf(b2a, x2), fminf(x1, b1a));
        b1a = fmaxf(b1a, x1);
        x1 = __shfl_xor_sync(0xffffffffu, b1b, o);
        x2 = __shfl_xor_sync(0xffffffffu, b2b, o);
        b2b = fmaxf(fmaxf(b2b, x2), fminf(x1, b1b));
        b1b = fmaxf(b1b, x1);
    }

    if (t == 0) {
        float ne = g_maxne, nle = g_maxnle;
        {   // pixel row g
            float nx = sqrtf(ssa), nlx = sqrtf(ssla);
            float thr = 2.0f * (nlx * ne + (nx + nlx) * nle)
                      + 2.44e-4f * (nx * ne + 0.5f * ne * ne) + 2e-3f;
            int n = p0 + w * 16 + g;
            if (b1a - b2a < thr) {
                ulonglong2 z = make_ulonglong2(0ull, 0ull);
                *(ulonglong2*)(g_fbres4 + 4 * n) = z;
                *(ulonglong2*)(g_fbres4 + 4 * n + 2) = z;
                g_fb_list[atomicAdd(&g_fb_count, 1)] = n;
            } else {
                int idx = __float_as_uint(b1a) & 1023;
                g_idx[n] = idx;
                out[IDX_OFF + n] = (float)idx;
            }
        }
        {   // pixel row g+8
            float nx = sqrtf(ssb), nlx = sqrtf(sslb);
            float thr = 2.0f * (nlx * ne + (nx + nlx) * nle)
                      + 2.44e-4f * (nx * ne + 0.5f * ne * ne) + 2e-3f;
            int n = p0 + w * 16 + g + 8;
            if (b1b - b2b < thr) {
                ulonglong2 z = make_ulonglong2(0ull, 0ull);
                *(ulonglong2*)(g_fbres4 + 4 * n) = z;
                *(ulonglong2*)(g_fbres4 + 4 * n + 2) = z;
                g_fb_list[atomicAdd(&g_fb_count, 1)] = n;
            } else {
                int idx = __float_as_uint(b1b) & 1023;
                g_idx[n] = idx;
                out[IDX_OFF + n] = (float)idx;
            }
        }
    }
}

// ---------------------------------------------------------------------------
// Kernel 2b: batched EXACT fp32 argmin, split-K x4. Unit = (128-px tile,
// quarter of codes). Persistent grid; per-pixel per-quarter packed result.
// ---------------------------------------------------------------------------
__global__ void __launch_bounds__(256) fbx_kernel(const float* __restrict__ in,
                                                  float* __restrict__ out) {
    __shared__ float  xs[64][128];    // 32KB
    __shared__ float4 es4[1024];      // 16KB
    const int tid = threadIdx.x;
    const int tx = tid & 7, ty = tid >> 3;
    const int count = g_fb_count;
    const int units = ((count + 127) >> 7) * 4;
    const float4* embT4 = (const float4*)g_embT;
    const float4* esqh4 = (const float4*)g_esqh;

    for (int u = blockIdx.x; u < units; u += gridDim.x) {
        const int tile = u >> 2, q = u & 3;
        const int pslot = tid & 127;
        int ii = tile * 128 + pslot;
        int n = g_fb_list[(ii < count) ? ii : (count - 1)];
        const float* ib = in + (size_t)(n >> 12) * 262144 + (n & 4095);

        __syncthreads();
        #pragma unroll
        for (int i = 0; i < 32; i++) {
            int d = (tid >> 7) + 2 * i;
            xs[d][pslot] = ib[(size_t)d * 4096];
        }

        float bestv[4]; int besti[4];
        #pragma unroll
        for (int i = 0; i < 4; i++) { bestv[i] = -3.4e38f; besti[i] = 0; }

        #pragma unroll
        for (int ck = 0; ck < 4; ck++) {
            const int ck2 = q * 4 + ck;
            __syncthreads();
            #pragma unroll
            for (int tt = 0; tt < 4; tt++) {
                int i = tid + tt * 256;
                es4[i] = embT4[(i >> 4) * 256 + ck2 * 16 + (i & 15)];
            }
            __syncthreads();

            float4 e0 = esqh4[ck2 * 16 + tx * 2], e1 = esqh4[ck2 * 16 + tx * 2 + 1];
            float acc[4][8];
            #pragma unroll
            for (int i = 0; i < 4; i++) {
                acc[i][0] = e0.x; acc[i][1] = e0.y; acc[i][2] = e0.z; acc[i][3] = e0.w;
                acc[i][4] = e1.x; acc[i][5] = e1.y; acc[i][6] = e1.z; acc[i][7] = e1.w;
            }
            #pragma unroll 8
            for (int d = 0; d < 64; d++) {
                float4 av = *(const float4*)&xs[d][ty * 4];
                float4 b0 = es4[d * 16 + tx * 2], b1v = es4[d * 16 + tx * 2 + 1];
                float a[4] = {av.x, av.y, av.z, av.w};
                float b[8] = {b0.x, b0.y, b0.z, b0.w, b1v.x, b1v.y, b1v.z, b1v.w};
                #pragma unroll
                for (int i = 0; i < 4; i++)
                    #pragma unroll
                    for (int j = 0; j < 8; j++) acc[i][j] = fmaf(a[i], b[j], acc[i][j]);
            }
            #pragma unroll
            for (int j = 0; j < 8; j++) {
                int kg = q * 256 + ck * 64 + tx * 8 + j;
                #pragma unroll
                for (int i = 0; i < 4; i++)
                    if (acc[i][j] > bestv[i]) { bestv[i] = acc[i][j]; besti[i] = kg; }
            }
        }

        #pragma unroll
        for (int i = 0; i < 4; i++) {
            float v = bestv[i]; int ix = besti[i];
            #pragma unroll
            for (int o = 4; o; o >>= 1) {
                float v2 = __shfl_xor_sync(0xffffffffu, v, o);
                int i2 = __shfl_xor_sync(0xffffffffu, ix, o);
                if (v2 > v || (v2 == v && i2 < ix)) { v = v2; ix = i2; }
            }
            if (tx == 0) {
                int gi = tile * 128 + ty * 4 + i;
                if (gi < count) {
                    int nn = g_fb_list[gi];
                    g_fbres4[4 * nn + q] = packord(v, ix);
                }
            }
        }
    }
}

// ---------------------------------------------------------------------------
// Kernel 2c: merge the four quarters, write final indices
// ---------------------------------------------------------------------------
__global__ void fbwrite_kernel(float* __restrict__ out) {
    int i = blockIdx.x * 256 + threadIdx.x;
    if (i >= g_fb_count) return;
    int n = g_fb_list[i];
    ulonglong2 r0 = *(const ulonglong2*)(g_fbres4 + 4 * n);
    ulonglong2 r1 = *(const ulonglong2*)(g_fbres4 + 4 * n + 2);
    u64 m = r0.x;
    if (r0.y > m) m = r0.y;
    if (r1.x > m) m = r1.x;
    if (r1.y > m) m = r1.y;
    int idx = 1023 - (int)(m & 1023u);
    g_idx[n] = idx;
    out[IDX_OFF + n] = (float)idx;
}

// ---------------------------------------------------------------------------
// Kernel 3: quantize — one thread per pixel
// ---------------------------------------------------------------------------
__global__ void quant_kernel(const float* __restrict__ in,
                             const float* __restrict__ embed,
                             float* __restrict__ out) {
    int n = blockIdx.x * 256 + threadIdx.x;
    int b = n >> 12, hw = n & 4095;
    int r = g_idx[n];

    const float4* er = (const float4*)(embed + r * 64);
    const float* ib = in + (size_t)b * 262144 + hw;
    float* ob = out + QUANT_OFF + (size_t)b * 262144 + hw;
    float* dwr = g_dwp + (blockIdx.x & 7) * 65536 + r * 64;

    float s = 0.0f;
    #pragma unroll
    for (int j = 0; j < 16; j++) {
        float4 q = __ldg(er + j);
        int d = j * 4;
        float x0 = ib[(size_t)d * 4096];
        float x1 = ib[(size_t)(d + 1) * 4096];
        float x2 = ib[(size_t)(d + 2) * 4096];
        float x3 = ib[(size_t)(d + 3) * 4096];
        ob[(size_t)d * 4096]       = q.x;
        ob[(size_t)(d + 1) * 4096] = q.y;
        ob[(size_t)(d + 2) * 4096] = q.z;
        ob[(size_t)(d + 3) * 4096] = q.w;
        float e0 = q.x - x0, e1 = q.y - x1, e2 = q.z - x2, e3 = q.w - x3;
        s += e0 * e0 + e1 * e1 + e2 * e2 + e3 * e3;
        red_v4(dwr + d, x0, x1, x2, x3);
    }
    atomicAdd(&g_counts[r], 1.0f);

    #pragma unroll
    for (int o = 16; o; o >>= 1) s += __shfl_down_sync(0xffffffffu, s, o);
    __shared__ float sm[8];
    if ((threadIdx.x & 31) == 0) sm[threadIdx.x >> 5] = s;
    __syncthreads();
    if (threadIdx.x == 0) {
        float tot = 0.0f;
        #pragma unroll
        for (int i = 0; i < 8; i++) tot += sm[i];
        atomicAdd(&g_loss, tot);
    }
}

// ---------------------------------------------------------------------------
// Kernel 4a: scalars
// ---------------------------------------------------------------------------
__global__ void scalar_kernel(const float* __restrict__ ema_cs, float* __restrict__ out) {
    __shared__ float s1[1024];
    __shared__ float s2[1024];
    int k = threadIdx.x;
    float cnt = g_counts[k];
    float ncs = 0.99f * ema_cs[k] + 0.01f * cnt;
    out[NCS_OFF + k] = ncs;
    float p = cnt * (1.0f / 131072.0f);
    s1[k] = ncs;
    s2[k] = p * logf(p + 1e-10f);
    __syncthreads();
    for (int o = 512; o; o >>= 1) {
        if (k < o) { s1[k] += s1[k + o]; s2[k] += s2[k + o]; }
        __syncthreads();
    }
    float nsum = s1[0];
    float csz = (ncs + 1e-5f) / (nsum + 1024.0f * 1e-5f) * nsum;
    g_scl[k] = fmaxf(csz, 1e-5f);
    if (k == 0) {
        out[LOSS_OFF] = 0.25f * g_loss * (1.0f / 8388608.0f);
        out[PERP_OFF] = expf(-s2[0]);
    }
}

// ---------------------------------------------------------------------------
// Kernel 4b: wide EMA update (sums the 8 dw replicas)
// ---------------------------------------------------------------------------
__global__ void ema_kernel(const float* __restrict__ ema_w, float* __restrict__ out) {
    int e = blockIdx.x * 512 + threadIdx.x;
    int kk = e >> 6;
    float dw = 0.0f;
    #pragma unroll
    for (int i = 0; i < 8; i++) dw += g_dwp[i * 65536 + e];
    float w = 0.99f * ema_w[e] + 0.01f * dw;
    out[NEMA_OFF + e] = w;
    out[NEMB_OFF + e] = w / g_scl[kk];
}

// ---------------------------------------------------------------------------
extern "C" void kernel_launch(void* const* d_in, const int* in_sizes, int n_in,
                              void* d_out, int out_size) {
    const float* in    = (const float*)d_in[0];
    const float* embed = (const float*)d_in[1];
    const float* ecs   = (const float*)d_in[2];
    const float* emw   = (const float*)d_in[3];
    float* out = (float*)d_out;

    prep_kernel<<<1024, 64>>>(embed);
    maxk_kernel<<<1, 1024>>>();
    argmin_mma<<<1024, 256>>>(in, out);
    fbx_kernel<<<592, 256>>>(in, out);
    fbwrite_kernel<<<512, 256>>>(out);
    quant_kernel<<<512, 256>>>(in, embed, out);
    scalar_kernel<<<1, 1024>>>(ecs, out);
    ema_kernel<<<128, 512>>>(emw, out);
}

// round 17
// speedup vs baseline: 1.5062x; 1.5062x over previous
#include <cuda_runtime.h>
#include <cuda_fp16.h>
#include <math.h>
#include <stdint.h>

#define N_PIX   131072
typedef unsigned long long u64;

// Output layout offsets (flattened tuple, float32) — total 8651778
#define QUANT_OFF 0
#define LOSS_OFF  8388608
#define PERP_OFF  8388609
#define IDX_OFF   8388610
#define NCS_OFF   8519682
#define NEMA_OFF  8520706
#define NEMB_OFF  8586242

// Scratch (device globals; no allocation allowed)
__device__ int   g_idx[N_PIX];
__device__ float g_embT[64 * 1024];                  // embT[d][k] for fbx
__device__ float g_esqh[1024];                       // -0.5*||e||^2
__device__ float g_lesq[1024];                       // ||e - hi(e)||^2
__device__ float g_counts[1024];
__device__ float g_dwp[8 * 65536];                   // 8-way privatized dw
__device__ float g_scl[1024];
__device__ float g_loss;
__device__ float g_maxne;                            // max_k ||e_k||
__device__ float g_maxnle;                           // max_k ||lo(e_k)||
// packed fp16-hi codebook: [chunk 16][kstep 4][n 64][j 8] half2
__device__ __align__(128) __half g_Bpk[16 * 4096];
__device__ int   g_fb_list[N_PIX];
__device__ int   g_fb_count;
__device__ u64   g_fbres2[N_PIX * 2];                // per-half exact packed results

// ---------------------------------------------------------------------------
// helpers (base PTX only)
// ---------------------------------------------------------------------------
__device__ __forceinline__ uint32_t smem_u32(const void* p) {
    uint32_t a;
    asm("{ .reg .u64 t; cvta.to.shared.u64 t, %1; cvt.u32.u64 %0, t; }" : "=r"(a) : "l"(p));
    return a;
}
__device__ __forceinline__ void mma16(float& d0, float& d1, float& d2, float& d3,
                                      const uint32_t* a, uint32_t b0, uint32_t b1) {
    asm volatile(
        "mma.sync.aligned.m16n8k16.row.col.f32.f16.f16.f32 "
        "{%0,%1,%2,%3}, {%4,%5,%6,%7}, {%8,%9}, {%0,%1,%2,%3};"
        : "+f"(d0), "+f"(d1), "+f"(d2), "+f"(d3)
        : "r"(a[0]), "r"(a[1]), "r"(a[2]), "r"(a[3]), "r"(b0), "r"(b1));
}
#define CP_ASYNC16(dst, src) \
    asm volatile("cp.async.cg.shared.global [%0], [%1], 16;" :: "r"(dst), "l"(src) : "memory")
#define CP_COMMIT() asm volatile("cp.async.commit_group;" ::: "memory")
#define CP_WAIT1()  asm volatile("cp.async.wait_group 1;" ::: "memory")
#define CP_WAIT0()  asm volatile("cp.async.wait_group 0;" ::: "memory")

__device__ __forceinline__ void red_v4(float* p, float a, float b, float c, float d) {
    asm volatile("red.global.add.v4.f32 [%0], {%1,%2,%3,%4};"
                 :: "l"(p), "f"(a), "f"(b), "f"(c), "f"(d) : "memory");
}
__device__ __forceinline__ uint32_t packh2(float x0, float x1) {
    __half2 hh = __halves2half2(__float2half_rn(x0), __float2half_rn(x1));
    return *(uint32_t*)&hh;
}
// pack score with code index in low 10 mantissa bits (branchless argmax carrier)
__device__ __forceinline__ float packsi(float s, int code) {
    return __uint_as_float((__float_as_uint(s) & 0xFFFFFC00u) | (uint32_t)code);
}
// branchless best-2 insert (b1 = max, b2 = runner-up)
__device__ __forceinline__ void best2(float& b1, float& b2, float s) {
    float t = fminf(s, b1);
    b1 = fmaxf(b1, s);
    b2 = fmaxf(b2, t);
}
// exact ordered encoding: u64 compare == (score desc, index asc) fp32 compare
__device__ __forceinline__ u64 packord(float s, int idx) {
    uint32_t u = __float_as_uint(s);
    u = (u & 0x80000000u) ? ~u : (u | 0x80000000u);
    return ((u64)u << 32) | (uint32_t)(1023 - idx);
}

// ---------------------------------------------------------------------------
// Kernel 1: prep — fp16-hi packed codebook, embT, esqh, lo-norms, zero accums
// ---------------------------------------------------------------------------
__global__ void prep_kernel(const float* __restrict__ embed) {
    int k = blockIdx.x;
    int t = threadIdx.x;
    float v = embed[k * 64 + t];
    g_embT[t * 1024 + k] = v;
    #pragma unroll
    for (int i = 0; i < 8; i++) g_dwp[i * 65536 + k * 64 + t] = 0.0f;

    __half hv = __float2half_rn(v);
    float lo = v - __half2float(hv);

    int c = k >> 6, n = k & 63, s = t >> 4, dl = t & 15, p = dl >> 1, h = dl & 1;
    int j = ((p & 3) << 1) | (p >> 2);
    g_Bpk[c * 4096 + (s * 64 + n) * 16 + j * 2 + h] = hv;

    float sq = v * v;
    float sql = lo * lo;
    #pragma unroll
    for (int o = 16; o; o >>= 1) {
        sq  += __shfl_down_sync(0xffffffffu, sq, o);
        sql += __shfl_down_sync(0xffffffffu, sql, o);
    }
    __shared__ float sm[2], sm2[2];
    if ((t & 31) == 0) { sm[t >> 5] = sq; sm2[t >> 5] = sql; }
    __syncthreads();
    if (t == 0) {
        g_esqh[k] = -0.5f * (sm[0] + sm[1]);
        g_lesq[k] = sm2[0] + sm2[1];
        g_counts[k] = 0.0f;
        if (k == 0) g_loss = 0.0f;
    }
}

// ---------------------------------------------------------------------------
// Kernel 1b: max norms + fb counter reset
// ---------------------------------------------------------------------------
__global__ void maxk_kernel() {
    __shared__ float sm[1024];
    __shared__ float sm2[1024];
    int t = threadIdx.x;
    sm[t] = g_esqh[t];
    sm2[t] = g_lesq[t];
    __syncthreads();
    for (int o = 512; o; o >>= 1) {
        if (t < o) {
            sm[t] = fminf(sm[t], sm[t + o]);
            sm2[t] = fmaxf(sm2[t], sm2[t + o]);
        }
        __syncthreads();
    }
    if (t == 0) {
        g_maxne = sqrtf(-2.0f * sm[0]);
        g_maxnle = sqrtf(sm2[0]);
        g_fb_count = 0;
    }
}

// ---------------------------------------------------------------------------
// Kernel 2: hh-only fp16 argmin via mma.sync; branchless packed best-2.
// Exact per-pixel lo-norm error bound; uncertain -> g_fb_list (+zeroed slots).
// ---------------------------------------------------------------------------
__global__ void __launch_bounds__(256) argmin_mma(const float* __restrict__ in,
                                                  float* __restrict__ out) {
    __shared__ __align__(16) __half Bsm[8192];    // 2 bufs x 8KB
    __shared__ float esqs[1024];
    uint32_t smb = smem_u32(Bsm);

    const int tid = threadIdx.x;
    const int w   = tid >> 5;
    const int ln  = tid & 31;
    const int g   = ln >> 2;
    const int t   = ln & 3;
    const int p0  = blockIdx.x * 128;
    const int bimg = p0 >> 12;
    const int hw0  = p0 & 4095;

    #pragma unroll
    for (int jj = 0; jj < 2; jj++) {
        int idx = tid + jj * 256;
        CP_ASYNC16(smb + idx * 16, (const char*)g_Bpk + idx * 16);
    }
    CP_COMMIT();

    #pragma unroll
    for (int i = 0; i < 4; i++) esqs[tid + i * 256] = g_esqh[tid + i * 256];

    uint32_t ah[4][4];
    float ssa = 0.0f, ssb = 0.0f, ssla = 0.0f, sslb = 0.0f;
    {
        const float* ap = in + (size_t)bimg * 262144 + hw0 + w * 16 + g;
        #pragma unroll
        for (int s = 0; s < 4; s++) {
            int d0 = 16 * s + 2 * t;
            float xa0 = ap[d0 * 4096],           xa1 = ap[(d0 + 1) * 4096];
            float xb0 = ap[d0 * 4096 + 8],       xb1 = ap[(d0 + 1) * 4096 + 8];
            float ya0 = ap[(d0 + 8) * 4096],     ya1 = ap[(d0 + 9) * 4096];
            float yb0 = ap[(d0 + 8) * 4096 + 8], yb1 = ap[(d0 + 9) * 4096 + 8];
            ah[s][0] = packh2(xa0, xa1);
            ah[s][1] = packh2(xb0, xb1);
            ah[s][2] = packh2(ya0, ya1);
            ah[s][3] = packh2(yb0, yb1);
            ssa += xa0 * xa0 + xa1 * xa1 + ya0 * ya0 + ya1 * ya1;
            ssb += xb0 * xb0 + xb1 * xb1 + yb0 * yb0 + yb1 * yb1;
            float l;
            l = xa0 - __half2float(__float2half_rn(xa0)); ssla += l * l;
            l = xa1 - __half2float(__float2half_rn(xa1)); ssla += l * l;
            l = ya0 - __half2float(__float2half_rn(ya0)); ssla += l * l;
            l = ya1 - __half2float(__float2half_rn(ya1)); ssla += l * l;
            l = xb0 - __half2float(__float2half_rn(xb0)); sslb += l * l;
            l = xb1 - __half2float(__float2half_rn(xb1)); sslb += l * l;
            l = yb0 - __half2float(__float2half_rn(yb0)); sslb += l * l;
            l = yb1 - __half2float(__float2half_rn(yb1)); sslb += l * l;
        }
        ssa += __shfl_xor_sync(0xffffffffu, ssa, 1);
        ssa += __shfl_xor_sync(0xffffffffu, ssa, 2);
        ssb += __shfl_xor_sync(0xffffffffu, ssb, 1);
        ssb += __shfl_xor_sync(0xffffffffu, ssb, 2);
        ssla += __shfl_xor_sync(0xffffffffu, ssla, 1);
        ssla += __shfl_xor_sync(0xffffffffu, ssla, 2);
        sslb += __shfl_xor_sync(0xffffffffu, sslb, 1);
        sslb += __shfl_xor_sync(0xffffffffu, sslb, 2);
    }

    float b1a = -3.4e38f, b2a = -3.4e38f;   // row g   (packed score|idx)
    float b1b = -3.4e38f, b2b = -3.4e38f;   // row g+8

    for (int c = 0; c < 16; c++) {
        const int buf = c & 1;
        if (c < 15) {
            int nb = (c + 1) & 1;
            #pragma unroll
            for (int jj = 0; jj < 2; jj++) {
                int idx = tid + jj * 256;
                CP_ASYNC16(smb + nb * 8192 + idx * 16,
                           (const char*)g_Bpk + (c + 1) * 8192 + idx * 16);
            }
            CP_COMMIT();
            CP_WAIT1();
        } else {
            CP_WAIT0();
        }
        __syncthreads();

        const uint32_t bb = smb + buf * 8192;
        const int kbase = c * 64;

        #pragma unroll
        for (int nt = 0; nt < 8; nt++) {
            const int nb_ = nt * 8 + g;
            const int code0 = kbase + nt * 8 + 2 * t;
            float e0 = esqs[code0], e1 = esqs[code0 + 1];
            float c0 = e0, c1 = e1, c2 = e0, c3 = e1;   // bias folded into accum
            #pragma unroll
            for (int s = 0; s < 4; s++) {
                uint32_t offh = bb + (s * 64 + nb_) * 32 + 8 * t;
                uint32_t bh0, bh1;
                asm volatile("ld.shared.v2.b32 {%0,%1}, [%2];" : "=r"(bh0), "=r"(bh1) : "r"(offh));
                mma16(c0, c1, c2, c3, ah[s], bh0, bh1);
            }
            best2(b1a, b2a, packsi(c0, code0));
            best2(b1a, b2a, packsi(c1, code0 + 1));
            best2(b1b, b2b, packsi(c2, code0));
            best2(b1b, b2b, packsi(c3, code0 + 1));
        }
        __syncthreads();
    }

    // merge best-2 across the 4 t-lanes
    #pragma unroll
    for (int o = 1; o <= 2; o <<= 1) {
        float x1 = __shfl_xor_sync(0xffffffffu, b1a, o);
        float x2 = __shfl_xor_sync(0xffffffffu, b2a, o);
        b2a = fmaxf(fmaxf(b2a, x2), fminf(x1, b1a));
        b1a = fmaxf(b1a, x1);
        x1 = __shfl_xor_sync(0xffffffffu, b1b, o);
        x2 = __shfl_xor_sync(0xffffffffu, b2b, o);
        b2b = fmaxf(fmaxf(b2b, x2), fminf(x1, b1b));
        b1b = fmaxf(b1b, x1);
    }

    if (t == 0) {
        float ne = g_maxne, nle = g_maxnle;
        {   // pixel row g
            float nx = sqrtf(ssa), nlx = sqrtf(ssla);
            float thr = 2.0f * (nlx * ne + (nx + nlx) * nle)
                      + 2.44e-4f * (nx * ne + 0.5f * ne * ne) + 2e-3f;
            int n = p0 + w * 16 + g;
            if (b1a - b2a < thr) {
                g_fbres2[2 * n] = 0ull;
                g_fbres2[2 * n + 1] = 0ull;
                g_fb_list[atomicAdd(&g_fb_count, 1)] = n;
            } else {
                int idx = __float_as_uint(b1a) & 1023;
                g_idx[n] = idx;
                out[IDX_OFF + n] = (float)idx;
            }
        }
        {   // pixel row g+8
            float nx = sqrtf(ssb), nlx = sqrtf(sslb);
            float thr = 2.0f * (nlx * ne + (nx + nlx) * nle)
                      + 2.44e-4f * (nx * ne + 0.5f * ne * ne) + 2e-3f;
            int n = p0 + w * 16 + g + 8;
            if (b1b - b2b < thr) {
                g_fbres2[2 * n] = 0ull;
                g_fbres2[2 * n + 1] = 0ull;
                g_fb_list[atomicAdd(&g_fb_count, 1)] = n;
            } else {
                int idx = __float_as_uint(b1b) & 1023;
                g_idx[n] = idx;
                out[IDX_OFF + n] = (float)idx;
            }
        }
    }
}

// ---------------------------------------------------------------------------
// Kernel 2b: batched EXACT fp32 argmin, split-K x2. Unit = (128-px tile, half
// of codes). Persistent grid, 3 blocks/SM; per-pixel per-half packed result.
// ---------------------------------------------------------------------------
__global__ void __launch_bounds__(256, 3) fbx_kernel(const float* __restrict__ in,
                                                     float* __restrict__ out) {
    __shared__ float  xs[64][128];    // 32KB
    __shared__ float4 es4[1024];      // 16KB
    const int tid = threadIdx.x;
    const int tx = tid & 7, ty = tid >> 3;
    const int count = g_fb_count;
    const int units = ((count + 127) >> 7) * 2;
    const float4* embT4 = (const float4*)g_embT;
    const float4* esqh4 = (const float4*)g_esqh;

    for (int u = blockIdx.x; u < units; u += gridDim.x) {
        const int tile = u >> 1, half = u & 1;
        const int pslot = tid & 127;
        int ii = tile * 128 + pslot;
        int n = g_fb_list[(ii < count) ? ii : (count - 1)];
        const float* ib = in + (size_t)(n >> 12) * 262144 + (n & 4095);

        __syncthreads();
        #pragma unroll
        for (int i = 0; i < 32; i++) {
            int d = (tid >> 7) + 2 * i;
            xs[d][pslot] = ib[(size_t)d * 4096];
        }

        float bestv[4]; int besti[4];
        #pragma unroll
        for (int i = 0; i < 4; i++) { bestv[i] = -3.4e38f; besti[i] = 0; }

        for (int ck = 0; ck < 8; ck++) {
            const int ck2 = half * 8 + ck;
            __syncthreads();
            #pragma unroll
            for (int tt = 0; tt < 4; tt++) {
                int i = tid + tt * 256;
                es4[i] = embT4[(i >> 4) * 256 + ck2 * 16 + (i & 15)];
            }
            __syncthreads();

            float4 e0 = esqh4[ck2 * 16 + tx * 2], e1 = esqh4[ck2 * 16 + tx * 2 + 1];
            float acc[4][8];
            #pragma unroll
            for (int i = 0; i < 4; i++) {
                acc[i][0] = e0.x; acc[i][1] = e0.y; acc[i][2] = e0.z; acc[i][3] = e0.w;
                acc[i][4] = e1.x; acc[i][5] = e1.y; acc[i][6] = e1.z; acc[i][7] = e1.w;
            }
            #pragma unroll 8
            for (int d = 0; d < 64; d++) {
                float4 av = *(const float4*)&xs[d][ty * 4];
                float4 b0 = es4[d * 16 + tx * 2], b1v = es4[d * 16 + tx * 2 + 1];
                float a[4] = {av.x, av.y, av.z, av.w};
                float b[8] = {b0.x, b0.y, b0.z, b0.w, b1v.x, b1v.y, b1v.z, b1v.w};
                #pragma unroll
                for (int i = 0; i < 4; i++)
                    #pragma unroll
                    for (int j = 0; j < 8; j++) acc[i][j] = fmaf(a[i], b[j], acc[i][j]);
            }
            #pragma unroll
            for (int j = 0; j < 8; j++) {
                int kg = half * 512 + ck * 64 + tx * 8 + j;
                #pragma unroll
                for (int i = 0; i < 4; i++)
                    if (acc[i][j] > bestv[i]) { bestv[i] = acc[i][j]; besti[i] = kg; }
            }
        }

        #pragma unroll
        for (int i = 0; i < 4; i++) {
            float v = bestv[i]; int ix = besti[i];
            #pragma unroll
            for (int o = 4; o; o >>= 1) {
                float v2 = __shfl_xor_sync(0xffffffffu, v, o);
                int i2 = __shfl_xor_sync(0xffffffffu, ix, o);
                if (v2 > v || (v2 == v && i2 < ix)) { v = v2; ix = i2; }
            }
            if (tx == 0) {
                int gi = tile * 128 + ty * 4 + i;
                if (gi < count) {
                    int nn = g_fb_list[gi];
                    g_fbres2[2 * nn + half] = packord(v, ix);
                }
            }
        }
    }
}

// ---------------------------------------------------------------------------
// Kernel 2c: merge the two halves, write final indices
// ---------------------------------------------------------------------------
__global__ void fbwrite_kernel(float* __restrict__ out) {
    int i = blockIdx.x * 256 + threadIdx.x;
    if (i >= g_fb_count) return;
    int n = g_fb_list[i];
    u64 a = g_fbres2[2 * n], b = g_fbres2[2 * n + 1];
    u64 m = (a > b) ? a : b;
    int idx = 1023 - (int)(m & 1023u);
    g_idx[n] = idx;
    out[IDX_OFF + n] = (float)idx;
}

// ---------------------------------------------------------------------------
// Kernel 3: quantize — one thread per pixel
// ---------------------------------------------------------------------------
__global__ void quant_kernel(const float* __restrict__ in,
                             const float* __restrict__ embed,
                             float* __restrict__ out) {
    int n = blockIdx.x * 256 + threadIdx.x;
    int b = n >> 12, hw = n & 4095;
    int r = g_idx[n];

    const float4* er = (const float4*)(embed + r * 64);
    const float* ib = in + (size_t)b * 262144 + hw;
    float* ob = out + QUANT_OFF + (size_t)b * 262144 + hw;
    float* dwr = g_dwp + (blockIdx.x & 7) * 65536 + r * 64;

    float s = 0.0f;
    #pragma unroll
    for (int j = 0; j < 16; j++) {
        float4 q = __ldg(er + j);
        int d = j * 4;
        float x0 = ib[(size_t)d * 4096];
        float x1 = ib[(size_t)(d + 1) * 4096];
        float x2 = ib[(size_t)(d + 2) * 4096];
        float x3 = ib[(size_t)(d + 3) * 4096];
        ob[(size_t)d * 4096]       = q.x;
        ob[(size_t)(d + 1) * 4096] = q.y;
        ob[(size_t)(d + 2) * 4096] = q.z;
        ob[(size_t)(d + 3) * 4096] = q.w;
        float e0 = q.x - x0, e1 = q.y - x1, e2 = q.z - x2, e3 = q.w - x3;
        s += e0 * e0 + e1 * e1 + e2 * e2 + e3 * e3;
        red_v4(dwr + d, x0, x1, x2, x3);
    }
    atomicAdd(&g_counts[r], 1.0f);

    #pragma unroll
    for (int o = 16; o; o >>= 1) s += __shfl_down_sync(0xffffffffu, s, o);
    __shared__ float sm[8];
    if ((threadIdx.x & 31) == 0) sm[threadIdx.x >> 5] = s;
    __syncthreads();
    if (threadIdx.x == 0) {
        float tot = 0.0f;
        #pragma unroll
        for (int i = 0; i < 8; i++) tot += sm[i];
        atomicAdd(&g_loss, tot);
    }
}

// ---------------------------------------------------------------------------
// Kernel 4a: scalars
// ---------------------------------------------------------------------------
__global__ void scalar_kernel(const float* __restrict__ ema_cs, float* __restrict__ out) {
    __shared__ float s1[1024];
    __shared__ float s2[1024];
    int k = threadIdx.x;
    float cnt = g_counts[k];
    float ncs = 0.99f * ema_cs[k] + 0.01f * cnt;
    out[NCS_OFF + k] = ncs;
    float p = cnt * (1.0f / 131072.0f);
    s1[k] = ncs;
    s2[k] = p * logf(p + 1e-10f);
    __syncthreads();
    for (int o = 512; o; o >>= 1) {
        if (k < o) { s1[k] += s1[k + o]; s2[k] += s2[k + o]; }
        __syncthreads();
    }
    float nsum = s1[0];
    float csz = (ncs + 1e-5f) / (nsum + 1024.0f * 1e-5f) * nsum;
    g_scl[k] = fmaxf(csz, 1e-5f);
    if (k == 0) {
        out[LOSS_OFF] = 0.25f * g_loss * (1.0f / 8388608.0f);
        out[PERP_OFF] = expf(-s2[0]);
    }
}

// ---------------------------------------------------------------------------
// Kernel 4b: wide EMA update (sums the 8 dw replicas)
// ---------------------------------------------------------------------------
__global__ void ema_kernel(const float* __restrict__ ema_w, float* __restrict__ out) {
    int e = blockIdx.x * 512 + threadIdx.x;
    int kk = e >> 6;
    float dw = 0.0f;
    #pragma unroll
    for (int i = 0; i < 8; i++) dw += g_dwp[i * 65536 + e];
    float w = 0.99f * ema_w[e] + 0.01f * dw;
    out[NEMA_OFF + e] = w;
    out[NEMB_OFF + e] = w / g_scl[kk];
}

// ---------------------------------------------------------------------------
extern "C" void kernel_launch(void* const* d_in, const int* in_sizes, int n_in,
                              void* d_out, int out_size) {
    const float* in    = (const float*)d_in[0];
    const float* embed = (const float*)d_in[1];
    const float* ecs   = (const float*)d_in[2];
    const float* emw   = (const float*)d_in[3];
    float* out = (float*)d_out;

    prep_kernel<<<1024, 64>>>(embed);
    maxk_kernel<<<1, 1024>>>();
    argmin_mma<<<1024, 256>>>(in, out);
    fbx_kernel<<<444, 256>>>(in, out);
    fbwrite_kernel<<<512, 256>>>(out);
    quant_kernel<<<512, 256>>>(in, embed, out);
    scalar_kernel<<<1, 1024>>>(ecs, out);
    ema_kernel<<<128, 512>>>(emw, out);
}